// round 5
// baseline (speedup 1.0000x reference)
#include <cuda_runtime.h>
#include <cuda_bf16.h>

// LightGCN 3-layer propagation. CSR (dst-sorted), atomic-free reduction.
// Preprocessing (3 kernels): histrank -> lookback-scan -> fill.
// Dtype detection is per-warp (consistent samples); cnt zeroing for the next
// replay is folded into prop<0>.

#define NUM_USERS 100000
#define NUM_ITEMS 50000
#define NN        150000
#define DIM       64
#define EDGES     1250000

#define NQ  (NN * 16)          // float4 count of one embedding buffer
#define UQ  (NUM_USERS * 16)

#define SCAN_B 256
#define NBLK   ((NN + SCAN_B - 1) / SCAN_B)   // 586
#define OFFSZ  (NBLK * SCAN_B)                // padded offset array size

// Device-global scratch. bufA/bufB = 77MB, edges = 10MB, rank = 5MB.
__device__ float    g_bufA[NN * DIM];
__device__ float    g_bufB[NN * DIM];
__device__ int      g_cnt [NN];        // in-degree (zeroed by prop<0> for next call)
__device__ int      g_rank[EDGES];     // per-edge arrival rank within its dst
__device__ int      g_off [OFFSZ + 1]; // ABSOLUTE exclusive prefix of cnt
__device__ unsigned g_desc[NBLK];      // lookback descriptors: state<<30 | value
__device__ int2     g_edge[EDGES];     // {src, __float_as_int(w)} sorted by dst

// ---------------------------------------------------------------------------
// Per-warp dtype detection: all warps sample the SAME first 8 int64 slots
// (one cache line) -> consistent verdict. int32 data read as int64 packs two
// random indices -> >= 2^32 unless the hi index is 0 (P ~ 7e-6 per sample).
// ---------------------------------------------------------------------------
__device__ __forceinline__ bool detect_is32(const void* edge) {
    int lid = threadIdx.x & 31;
    bool bad = false;
    if (lid < 8) {
        long long v = ((const long long*)edge)[lid];
        bad = (v < 0 || v >= (long long)NN);
    }
    return __ballot_sync(0xffffffffu, bad) != 0;
}

// ---------------------------------------------------------------------------
// histogram + per-edge rank; also zero the lookback descriptors for the scan.
// ---------------------------------------------------------------------------
__global__ void histrank_kernel(const void* edge) {
    int e = blockIdx.x * blockDim.x + threadIdx.x;
    if (e < NBLK) g_desc[e] = 0;
    if (e >= EDGES) return;
    bool is32 = detect_is32(edge);
    int d;
    if (is32) d = ((const int*)edge)[EDGES + e];
    else      d = (int)((const long long*)edge)[EDGES + e];
    g_rank[e] = atomicAdd(&g_cnt[d], 1);
}

// ---------------------------------------------------------------------------
// Single-kernel exclusive scan (decoupled lookback), absolute offsets out.
// ---------------------------------------------------------------------------
__device__ __forceinline__ int warp_incl_scan(int v, int lid) {
    #pragma unroll
    for (int o = 1; o < 32; o <<= 1) {
        int t = __shfl_up_sync(0xffffffffu, v, o);
        if (lid >= o) v += t;
    }
    return v;
}

__global__ void __launch_bounds__(SCAN_B)
scan_kernel() {
    __shared__ int wsum[8];
    __shared__ int s_exc;
    int b = blockIdx.x;
    int i = b * SCAN_B + threadIdx.x;
    int v = (i < NN) ? g_cnt[i] : 0;
    int lid = threadIdx.x & 31, wid = threadIdx.x >> 5;
    int incl = warp_incl_scan(v, lid);
    if (lid == 31) wsum[wid] = incl;
    __syncthreads();
    if (wid == 0) {
        int s = (lid < 8) ? wsum[lid] : 0;
        #pragma unroll
        for (int o = 1; o < 8; o <<= 1) {
            int t = __shfl_up_sync(0xffffffffu, s, o);
            if (lid >= o) s += t;
        }
        if (lid < 8) wsum[lid] = s;
    }
    __syncthreads();
    int base = (wid > 0) ? wsum[wid - 1] : 0;
    int tot  = wsum[7];                    // block aggregate

    // publish
    if (threadIdx.x == 0) {
        if (b == 0) {
            s_exc = 0;
            atomicExch(&g_desc[0], (2u << 30) | (unsigned)tot);   // prefix
        } else {
            atomicExch(&g_desc[b], (1u << 30) | (unsigned)tot);   // aggregate
        }
    }

    // lookback (warp 0 of blocks > 0)
    if (b > 0 && wid == 0) {
        int exc = 0;
        int idx = b - 1;
        while (true) {
            int p = idx - lid;
            unsigned d = (p >= 0) ? atomicOr(&g_desc[p], 0u) : (2u << 30);
            unsigned st  = d >> 30;
            unsigned val = d & 0x3FFFFFFFu;
            unsigned pmask = __ballot_sync(0xffffffffu, st == 2);
            unsigned zmask = __ballot_sync(0xffffffffu, st == 0);
            if (pmask) {
                int L = __ffs(pmask) - 1;               // closest prefix
                if ((zmask & ((1u << L) - 1)) == 0) {   // all nearer are ready
                    unsigned contrib = (lid <= L) ? val : 0;
                    #pragma unroll
                    for (int o = 16; o; o >>= 1)
                        contrib += __shfl_down_sync(0xffffffffu, contrib, o);
                    exc += (int)__shfl_sync(0xffffffffu, contrib, 0);
                    break;
                }
            } else if (zmask == 0) {                    // 32 aggregates: keep going
                unsigned contrib = val;
                #pragma unroll
                for (int o = 16; o; o >>= 1)
                    contrib += __shfl_down_sync(0xffffffffu, contrib, o);
                exc += (int)__shfl_sync(0xffffffffu, contrib, 0);
                idx -= 32;
            }
            // else: not ready yet, spin
        }
        if (lid == 0) {
            s_exc = exc;
            atomicExch(&g_desc[b], (2u << 30) | (unsigned)(exc + tot));
        }
    }
    __syncthreads();
    g_off[i] = s_exc + base + incl - v;    // absolute exclusive prefix
}

// ---------------------------------------------------------------------------
// CSR fill: pos = g_off[d] + rank[e]. No atomics.
// w = rsqrt(deg_s*deg_d), 0-guarded.
// ---------------------------------------------------------------------------
__global__ void fill_kernel(const void* edge) {
    int e = blockIdx.x * blockDim.x + threadIdx.x;
    if (e >= EDGES) return;
    bool is32 = detect_is32(edge);
    int s, d;
    if (is32) {
        const int* ei = (const int*)edge;
        s = ei[e];
        d = ei[EDGES + e];
    } else {
        const long long* ei = (const long long*)edge;
        s = (int)ei[e];
        d = (int)ei[EDGES + e];
    }
    float p = (float)g_cnt[s] * (float)g_cnt[d];
    float w = (p > 0.f) ? rsqrtf(p) : 0.f;
    int pos = g_off[d] + g_rank[e];
    g_edge[pos] = make_int2(s, __float_as_int(w));
}

// ---------------------------------------------------------------------------
// Propagate. 16 lanes per node; lane c owns float4 #c of the 64-float row.
// MODE 0: layer 1 (gather from uw/iw) -> nxt; also re-zeroes g_cnt for the
//         next replay (safe: runs after fill, the last cnt consumer).
// MODE 1: middle (gather from cur) -> nxt.
// MODE 2: final: out = (emb + c1 + cur + r)/4, duplicated.
// ---------------------------------------------------------------------------
template<int MODE>
__device__ __forceinline__ float4 gather(const float* __restrict__ cur,
                                         const float* __restrict__ uw,
                                         const float* __restrict__ iw,
                                         int s, int c) {
    if (MODE == 0) {
        const float4* base = (s < NUM_USERS)
            ? (const float4*)uw + (long long)s * 16
            : (const float4*)iw + (long long)(s - NUM_USERS) * 16;
        return base[c];
    }
    return ((const float4*)cur)[(long long)s * 16 + c];
}

template<int MODE>
__global__ void __launch_bounds__(256)
prop_kernel(const float* __restrict__ cur,
            const float* __restrict__ uw,
            const float* __restrict__ iw,
            const float* __restrict__ c1,
            float* __restrict__ nxt,
            float* __restrict__ out) {
    int t = blockIdx.x * blockDim.x + threadIdx.x;
    if (MODE == 0 && t < NN) g_cnt[t] = 0;     // reset for next call
    int n = t >> 4;
    int c = t & 15;
    if (n >= NN) return;
    int j   = g_off[n];
    int end = g_off[n + 1];
    float4 r = make_float4(0.f, 0.f, 0.f, 0.f);

    const int2* __restrict__ ge = g_edge;
    for (; j + 4 <= end; j += 4) {
        int2 e0 = ge[j];
        int2 e1 = ge[j + 1];
        int2 e2 = ge[j + 2];
        int2 e3 = ge[j + 3];
        float4 v0 = gather<MODE>(cur, uw, iw, e0.x, c);
        float4 v1 = gather<MODE>(cur, uw, iw, e1.x, c);
        float4 v2 = gather<MODE>(cur, uw, iw, e2.x, c);
        float4 v3 = gather<MODE>(cur, uw, iw, e3.x, c);
        float w0 = __int_as_float(e0.y), w1 = __int_as_float(e1.y);
        float w2 = __int_as_float(e2.y), w3 = __int_as_float(e3.y);
        r.x += v0.x * w0 + v1.x * w1 + v2.x * w2 + v3.x * w3;
        r.y += v0.y * w0 + v1.y * w1 + v2.y * w2 + v3.y * w3;
        r.z += v0.z * w0 + v1.z * w1 + v2.z * w2 + v3.z * w3;
        r.w += v0.w * w0 + v1.w * w1 + v2.w * w2 + v3.w * w3;
    }
    #pragma unroll 1
    for (; j < end; ++j) {
        int2 e0 = ge[j];
        float w0 = __int_as_float(e0.y);
        float4 v0 = gather<MODE>(cur, uw, iw, e0.x, c);
        r.x += v0.x * w0; r.y += v0.y * w0; r.z += v0.z * w0; r.w += v0.w * w0;
    }

    int idx = n * 16 + c;
    if (MODE == 2) {
        float4 e = (n < NUM_USERS) ? ((const float4*)uw)[idx]
                                   : ((const float4*)iw)[idx - UQ];
        float4 a = ((const float4*)c1)[idx];   // layer-1 result
        float4 b = ((const float4*)cur)[idx];  // layer-2 result
        float4 o;
        o.x = (e.x + a.x + b.x + r.x) * 0.25f;
        o.y = (e.y + a.y + b.y + r.y) * 0.25f;
        o.z = (e.z + a.z + b.z + r.z) * 0.25f;
        o.w = (e.w + a.w + b.w + r.w) * 0.25f;
        float4* op = (float4*)out;
        op[idx]      = o;
        op[NQ + idx] = o;
    } else {
        ((float4*)nxt)[idx] = r;
    }
}

// ---------------------------------------------------------------------------
extern "C" void kernel_launch(void* const* d_in, const int* in_sizes, int n_in,
                              void* d_out, int out_size) {
    const void*  edge = d_in[0];
    const float* uw   = (const float*)d_in[1];
    const float* iw   = (const float*)d_in[2];
    float*       out  = (float*)d_out;

    float* A = nullptr;
    float* B = nullptr;
    cudaGetSymbolAddress((void**)&A, g_bufA);
    cudaGetSymbolAddress((void**)&B, g_bufB);

    const int T = 256;
    const int grid_e = (EDGES + T - 1) / T;
    const int grid_p = (NN * 16 + T - 1) / T;

    histrank_kernel<<<grid_e, T>>>(edge);
    scan_kernel<<<NBLK, SCAN_B>>>();
    fill_kernel<<<grid_e, T>>>(edge);

    // layer 1: emb -> B (c1); also resets g_cnt
    prop_kernel<0><<<grid_p, T>>>(nullptr, uw, iw, nullptr, B, nullptr);
    // layer 2: B -> A (c2)
    prop_kernel<1><<<grid_p, T>>>(B, nullptr, nullptr, nullptr, A, nullptr);
    // layer 3: gather A, finalize with emb + B + A, duplicated output
    prop_kernel<2><<<grid_p, T>>>(A, uw, iw, B, nullptr, out);
}

// round 6
// speedup vs baseline: 1.1388x; 1.1388x over previous
#include <cuda_runtime.h>
#include <cuda_bf16.h>

// LightGCN 3-layer propagation. CSR (dst-sorted), atomic-free reduction.
// Preprocessing (4 kernels): histrank -> scan1 -> scan2 -> fill.
// Dtype detect inline per-warp; g_cnt re-zeroed inside prop<0>.

#define NUM_USERS 100000
#define NUM_ITEMS 50000
#define NN        150000
#define DIM       64
#define EDGES     1250000

#define NQ  (NN * 16)          // float4 count of one embedding buffer
#define UQ  (NUM_USERS * 16)

#define SCAN_B 256
#define NBLK   ((NN + SCAN_B - 1) / SCAN_B)   // 586
#define OFFSZ  (NBLK * SCAN_B)

// Device-global scratch. bufA/bufB = 77MB, edges = 10MB, rank = 5MB.
__device__ float g_bufA[NN * DIM];
__device__ float g_bufB[NN * DIM];
__device__ int   g_cnt [NN];        // in-degree (zeroed by prop<0> for next call)
__device__ int   g_rank[EDGES];     // per-edge arrival rank within its dst
__device__ int   g_off [OFFSZ + 1]; // block-LOCAL exclusive prefix of cnt
__device__ int   g_bsum[NBLK];      // exclusive block sums
__device__ int2  g_edge[EDGES];     // {src, __float_as_int(w)} sorted by dst

// ---------------------------------------------------------------------------
// Per-warp dtype detection: all warps sample the SAME first 8 int64 slots
// (one cache line) -> consistent verdict chip-wide.
// ---------------------------------------------------------------------------
__device__ __forceinline__ bool detect_is32(const void* edge) {
    int lid = threadIdx.x & 31;
    bool bad = false;
    if (lid < 8) {
        long long v = ((const long long*)edge)[lid];
        bad = (v < 0 || v >= (long long)NN);
    }
    return __ballot_sync(0xffffffffu, bad) != 0;
}

// ---------------------------------------------------------------------------
// histogram + per-edge rank (atomicAdd return value)
// ---------------------------------------------------------------------------
__global__ void histrank_kernel(const void* edge) {
    int e = blockIdx.x * blockDim.x + threadIdx.x;
    if (e >= EDGES) return;
    bool is32 = detect_is32(edge);
    int d;
    if (is32) d = ((const int*)edge)[EDGES + e];
    else      d = (int)((const long long*)edge)[EDGES + e];
    g_rank[e] = atomicAdd(&g_cnt[d], 1);
}

// ---------------------------------------------------------------------------
// two-phase shuffle scan (block-local exclusive + exclusive block sums)
// ---------------------------------------------------------------------------
__device__ __forceinline__ int warp_incl_scan(int v, int lid) {
    #pragma unroll
    for (int o = 1; o < 32; o <<= 1) {
        int t = __shfl_up_sync(0xffffffffu, v, o);
        if (lid >= o) v += t;
    }
    return v;
}

__global__ void scan1_kernel() {
    __shared__ int wsum[8];
    int i = blockIdx.x * SCAN_B + threadIdx.x;
    int v = (i < NN) ? g_cnt[i] : 0;
    int wid = threadIdx.x >> 5, lid = threadIdx.x & 31;
    int incl = warp_incl_scan(v, lid);
    if (lid == 31) wsum[wid] = incl;
    __syncthreads();
    if (wid == 0) {
        int s = (lid < 8) ? wsum[lid] : 0;
        #pragma unroll
        for (int o = 1; o < 8; o <<= 1) {
            int t = __shfl_up_sync(0xffffffffu, s, o);
            if (lid >= o) s += t;
        }
        if (lid < 8) wsum[lid] = s;
    }
    __syncthreads();
    int base = (wid > 0) ? wsum[wid - 1] : 0;
    g_off[i] = base + incl - v;                        // block-local exclusive
    if (threadIdx.x == SCAN_B - 1) g_bsum[blockIdx.x] = base + incl;
    if (i == 0) g_off[OFFSZ] = 0;
}

__global__ void scan2_kernel() {   // 1 block, NBLK=586 elements, 640 threads
    __shared__ int wsum[20];
    int i = threadIdx.x;
    int lid = i & 31, wid = i >> 5;
    int v = (i < NBLK) ? g_bsum[i] : 0;
    int incl = warp_incl_scan(v, lid);
    if (lid == 31) wsum[wid] = incl;
    __syncthreads();
    if (wid == 0) {
        int s = (lid < 20) ? wsum[lid] : 0;
        #pragma unroll
        for (int o = 1; o < 32; o <<= 1) {
            int t = __shfl_up_sync(0xffffffffu, s, o);
            if (lid >= o) s += t;
        }
        if (lid < 20) wsum[lid] = s;
    }
    __syncthreads();
    int base = (wid > 0) ? wsum[wid - 1] : 0;
    if (i < NBLK) g_bsum[i] = base + incl - v;         // exclusive block prefix
}

// ---------------------------------------------------------------------------
// CSR fill: pos = local_off[d] + bsum[d>>8] + rank[e]. No atomics.
// ---------------------------------------------------------------------------
__global__ void fill_kernel(const void* edge) {
    int e = blockIdx.x * blockDim.x + threadIdx.x;
    if (e >= EDGES) return;
    bool is32 = detect_is32(edge);
    int s, d;
    if (is32) {
        const int* ei = (const int*)edge;
        s = ei[e];
        d = ei[EDGES + e];
    } else {
        const long long* ei = (const long long*)edge;
        s = (int)ei[e];
        d = (int)ei[EDGES + e];
    }
    float p = (float)g_cnt[s] * (float)g_cnt[d];
    float w = (p > 0.f) ? rsqrtf(p) : 0.f;
    int pos = g_off[d] + g_bsum[d >> 8] + g_rank[e];
    g_edge[pos] = make_int2(s, __float_as_int(w));
}

// ---------------------------------------------------------------------------
// Propagate. 16 lanes per node; lane c owns float4 #c of the 64-float row.
// Edge list consumed as int4 pairs (2 edges / LDG.128), 6 edges per iter.
// MODE 0: layer 1 (gather from uw/iw) -> nxt; re-zeroes g_cnt.
// MODE 1: middle (gather from cur) -> nxt.
// MODE 2: final: out = (emb + c1 + cur + r)/4, duplicated.
// ---------------------------------------------------------------------------
template<int MODE>
__device__ __forceinline__ float4 gather(const float* __restrict__ cur,
                                         const float* __restrict__ uw,
                                         const float* __restrict__ iw,
                                         int s, int c) {
    if (MODE == 0) {
        const float4* base = (s < NUM_USERS)
            ? (const float4*)uw + s * 16
            : (const float4*)iw + (s - NUM_USERS) * 16;
        return base[c];
    }
    return ((const float4*)cur)[s * 16 + c];
}

template<int MODE>
__global__ void __launch_bounds__(256)
prop_kernel(const float* __restrict__ cur,
            const float* __restrict__ uw,
            const float* __restrict__ iw,
            const float* __restrict__ c1,
            float* __restrict__ nxt,
            float* __restrict__ out) {
    int t = blockIdx.x * blockDim.x + threadIdx.x;
    if (MODE == 0 && t < NN) g_cnt[t] = 0;     // reset for next replay
    int n = t >> 4;
    int c = t & 15;
    if (n >= NN) return;
    int j   = g_off[n]     + g_bsum[n >> 8];
    int end = g_off[n + 1] + g_bsum[(n + 1) >> 8];
    float4 r = make_float4(0.f, 0.f, 0.f, 0.f);

    // align to pair boundary
    if (j < end && (j & 1)) {
        int2 e0 = g_edge[j];
        float w0 = __int_as_float(e0.y);
        float4 v0 = gather<MODE>(cur, uw, iw, e0.x, c);
        r.x += v0.x * w0; r.y += v0.y * w0; r.z += v0.z * w0; r.w += v0.w * w0;
        ++j;
    }
    int npair = (end - j) >> 1;
    const int4* __restrict__ gp = (const int4*)g_edge + (j >> 1);
    int k = 0;
    for (; k + 3 <= npair; k += 3) {           // 6 edges / iteration
        int4 p0 = gp[k];
        int4 p1 = gp[k + 1];
        int4 p2 = gp[k + 2];
        float4 v0 = gather<MODE>(cur, uw, iw, p0.x, c);
        float4 v1 = gather<MODE>(cur, uw, iw, p0.z, c);
        float4 v2 = gather<MODE>(cur, uw, iw, p1.x, c);
        float4 v3 = gather<MODE>(cur, uw, iw, p1.z, c);
        float4 v4 = gather<MODE>(cur, uw, iw, p2.x, c);
        float4 v5 = gather<MODE>(cur, uw, iw, p2.z, c);
        float w0 = __int_as_float(p0.y), w1 = __int_as_float(p0.w);
        float w2 = __int_as_float(p1.y), w3 = __int_as_float(p1.w);
        float w4 = __int_as_float(p2.y), w5 = __int_as_float(p2.w);
        r.x += v0.x * w0 + v1.x * w1 + v2.x * w2 + v3.x * w3 + v4.x * w4 + v5.x * w5;
        r.y += v0.y * w0 + v1.y * w1 + v2.y * w2 + v3.y * w3 + v4.y * w4 + v5.y * w5;
        r.z += v0.z * w0 + v1.z * w1 + v2.z * w2 + v3.z * w3 + v4.z * w4 + v5.z * w5;
        r.w += v0.w * w0 + v1.w * w1 + v2.w * w2 + v3.w * w3 + v4.w * w4 + v5.w * w5;
    }
    #pragma unroll 1
    for (; k < npair; ++k) {                   // leftover pairs
        int4 p0 = gp[k];
        float4 v0 = gather<MODE>(cur, uw, iw, p0.x, c);
        float4 v1 = gather<MODE>(cur, uw, iw, p0.z, c);
        float w0 = __int_as_float(p0.y), w1 = __int_as_float(p0.w);
        r.x += v0.x * w0 + v1.x * w1;
        r.y += v0.y * w0 + v1.y * w1;
        r.z += v0.z * w0 + v1.z * w1;
        r.w += v0.w * w0 + v1.w * w1;
    }
    if ((end - j) & 1) {                       // trailing odd edge
        int2 e0 = g_edge[end - 1];
        float w0 = __int_as_float(e0.y);
        float4 v0 = gather<MODE>(cur, uw, iw, e0.x, c);
        r.x += v0.x * w0; r.y += v0.y * w0; r.z += v0.z * w0; r.w += v0.w * w0;
    }

    int idx = n * 16 + c;
    if (MODE == 2) {
        float4 e = (n < NUM_USERS) ? ((const float4*)uw)[idx]
                                   : ((const float4*)iw)[idx - UQ];
        float4 a = ((const float4*)c1)[idx];   // layer-1 result
        float4 b = ((const float4*)cur)[idx];  // layer-2 result
        float4 o;
        o.x = (e.x + a.x + b.x + r.x) * 0.25f;
        o.y = (e.y + a.y + b.y + r.y) * 0.25f;
        o.z = (e.z + a.z + b.z + r.z) * 0.25f;
        o.w = (e.w + a.w + b.w + r.w) * 0.25f;
        float4* op = (float4*)out;
        op[idx]      = o;
        op[NQ + idx] = o;
    } else {
        ((float4*)nxt)[idx] = r;
    }
}

// ---------------------------------------------------------------------------
extern "C" void kernel_launch(void* const* d_in, const int* in_sizes, int n_in,
                              void* d_out, int out_size) {
    const void*  edge = d_in[0];
    const float* uw   = (const float*)d_in[1];
    const float* iw   = (const float*)d_in[2];
    float*       out  = (float*)d_out;

    float* A = nullptr;
    float* B = nullptr;
    cudaGetSymbolAddress((void**)&A, g_bufA);
    cudaGetSymbolAddress((void**)&B, g_bufB);

    const int T = 256;
    const int grid_e = (EDGES + T - 1) / T;
    const int grid_p = (NN * 16 + T - 1) / T;

    histrank_kernel<<<grid_e, T>>>(edge);
    scan1_kernel<<<NBLK, SCAN_B>>>();
    scan2_kernel<<<1, 640>>>();
    fill_kernel<<<grid_e, T>>>(edge);

    // layer 1: emb -> B (c1); also resets g_cnt
    prop_kernel<0><<<grid_p, T>>>(nullptr, uw, iw, nullptr, B, nullptr);
    // layer 2: B -> A (c2)
    prop_kernel<1><<<grid_p, T>>>(B, nullptr, nullptr, nullptr, A, nullptr);
    // layer 3: gather A, finalize with emb + B + A, duplicated output
    prop_kernel<2><<<grid_p, T>>>(A, uw, iw, B, nullptr, out);
}